// round 14
// baseline (speedup 1.0000x reference)
#include <cuda_runtime.h>
#include <cstddef>

#define D_DIM   64
#define N_USERS 4096
#define N_ITEMS 16384
#define L_U     50
#define L_I     20
#define OUT_W   (D_DIM + 2)   // 66
#define N_ROWS  (N_USERS + N_ITEMS)
#define THREADS 128
#define N_IPAIR (N_ITEMS / 2)            // 8192 item-pair warps
#define N_WARPS (N_USERS + N_IPAIR)      // 12288 total warps

// ---------- user row: one warp, 50 gathers (proven R2 body) ----------
__device__ __forceinline__
void user_row(const float* __restrict__ emb,
              const float* __restrict__ w,
              float                     bias,
              const float* __restrict__ h1,
              const int*   __restrict__ my_idx,
              float*       __restrict__ orow,
              int lane)
{
    int idx_lo = my_idx[lane];
    int idx_hi = (lane + 32 < L_U) ? my_idx[lane + 32] : 0;

    float wsum = __ldg(&w[idx_lo]);
    if (lane + 32 < L_U) wsum += __ldg(&w[idx_hi]);

    float sx = 0.f, sy = 0.f, qx = 0.f, qy = 0.f;

    #pragma unroll
    for (int j = 0; j < L_U; ++j) {
        int src = (j < 32) ? idx_lo : idx_hi;
        int r   = __shfl_sync(0xffffffffu, src, j & 31);
        float2 g = *reinterpret_cast<const float2*>(emb + (size_t)r * D_DIM + 2 * lane);
        sx += g.x; sy += g.y;
        qx += g.x * g.x; qy += g.y * g.y;
    }

    float2 h = *reinterpret_cast<const float2*>(h1 + 2 * lane);
    float part = 0.5f * (sx * sx - qx) * h.x
               + 0.5f * (sy * sy - qy) * h.y + wsum;

    #pragma unroll
    for (int o = 16; o > 0; o >>= 1)
        part += __shfl_xor_sync(0xffffffffu, part, o);

    float2 sv; sv.x = sx; sv.y = sy;
    *reinterpret_cast<float2*>(orow + 2 * lane) = sv;
    if (lane == 0) {
        orow[D_DIM]     = part + bias;
        orow[D_DIM + 1] = 1.0f;
    }
}

// ---------- item pair: one warp, two independent rows (2x20 gathers) ----------
__device__ __forceinline__
void item_pair(const float* __restrict__ emb,
               const float* __restrict__ w,
               const float* __restrict__ h1,
               const int*   __restrict__ idx_a,   // row 2p
               const int*   __restrict__ idx_b,   // row 2p+1
               float*       __restrict__ orow_a,
               float*       __restrict__ orow_b,
               int lane)
{
    int ia = (lane < L_I) ? idx_a[lane] : 0;
    int ib = (lane < L_I) ? idx_b[lane] : 0;

    float wa = (lane < L_I) ? __ldg(&w[ia]) : 0.f;
    float wb = (lane < L_I) ? __ldg(&w[ib]) : 0.f;

    float sax = 0.f, say = 0.f, qax = 0.f, qay = 0.f;
    float sbx = 0.f, sby = 0.f, qbx = 0.f, qby = 0.f;

    #pragma unroll
    for (int j = 0; j < L_I; ++j) {
        int ra = __shfl_sync(0xffffffffu, ia, j);
        int rb = __shfl_sync(0xffffffffu, ib, j);
        float2 ga = *reinterpret_cast<const float2*>(emb + (size_t)ra * D_DIM + 2 * lane);
        float2 gb = *reinterpret_cast<const float2*>(emb + (size_t)rb * D_DIM + 2 * lane);
        sax += ga.x; say += ga.y; qax += ga.x * ga.x; qay += ga.y * ga.y;
        sbx += gb.x; sby += gb.y; qbx += gb.x * gb.x; qby += gb.y * gb.y;
    }

    float2 h = *reinterpret_cast<const float2*>(h1 + 2 * lane);

    float pa = 0.5f * (sax * sax - qax) * h.x
             + 0.5f * (say * say - qay) * h.y + wa;
    float pb = 0.5f * (sbx * sbx - qbx) * h.x
             + 0.5f * (sby * sby - qby) * h.y + wb;

    #pragma unroll
    for (int o = 16; o > 0; o >>= 1) {
        pa += __shfl_xor_sync(0xffffffffu, pa, o);
        pb += __shfl_xor_sync(0xffffffffu, pb, o);
    }

    float2 sva; sva.x = sax; sva.y = say;
    float2 svb; svb.x = sbx; svb.y = sby;
    *reinterpret_cast<float2*>(orow_a + 2 * lane) = sva;
    *reinterpret_cast<float2*>(orow_b + 2 * lane) = svb;

    if (lane == 0) {
        orow_a[D_DIM] = 1.0f; orow_a[D_DIM + 1] = pa;
        orow_b[D_DIM] = 1.0f; orow_b[D_DIM + 1] = pb;
    }
}

__global__ __launch_bounds__(THREADS)
void fm_ilp_kernel(const float* __restrict__ uemb,
                   const float* __restrict__ iemb,
                   const float* __restrict__ uw,
                   const float* __restrict__ iw,
                   const float* __restrict__ gbias,
                   const float* __restrict__ h1,
                   const float* __restrict__ h2,
                   const int*   __restrict__ uidx,
                   const int*   __restrict__ iidx,
                   float*       __restrict__ out)
{
    const int lane = threadIdx.x & 31;
    const int gw   = (blockIdx.x * blockDim.x + threadIdx.x) >> 5;

    if (blockIdx.x == 0 && threadIdx.x < D_DIM) {
        out[(size_t)N_ROWS * OUT_W + threadIdx.x] = h2[threadIdx.x];
    }

    if (gw < N_USERS) {
        user_row(uemb, uw, gbias[0], h1,
                 uidx + (size_t)gw * L_U,
                 out + (size_t)gw * OUT_W, lane);
    } else if (gw < N_WARPS) {
        const int p  = gw - N_USERS;
        const int ra = 2 * p;
        const int rb = 2 * p + 1;
        item_pair(iemb, iw, h1,
                  iidx + (size_t)ra * L_I,
                  iidx + (size_t)rb * L_I,
                  out + (size_t)(N_USERS + ra) * OUT_W,
                  out + (size_t)(N_USERS + rb) * OUT_W,
                  lane);
    }
}

extern "C" void kernel_launch(void* const* d_in, const int* in_sizes, int n_in,
                              void* d_out, int out_size)
{
    const float* uemb  = (const float*)d_in[0];
    const float* iemb  = (const float*)d_in[1];
    const float* uw    = (const float*)d_in[2];
    const float* iw    = (const float*)d_in[3];
    const float* gbias = (const float*)d_in[4];
    const float* h1    = (const float*)d_in[5];
    const float* h2    = (const float*)d_in[6];
    const int*   uidx  = (const int*)d_in[7];
    const int*   iidx  = (const int*)d_in[8];

    float* out = (float*)d_out;

    const int warps_per_block = THREADS / 32;                                // 4
    const int blocks = (N_WARPS + warps_per_block - 1) / warps_per_block;    // 3072

    fm_ilp_kernel<<<blocks, THREADS>>>(uemb, iemb, uw, iw, gbias, h1, h2,
                                       uidx, iidx, out);
}

// round 15
// speedup vs baseline: 1.0493x; 1.0493x over previous
#include <cuda_runtime.h>
#include <cstddef>

#define D_DIM   64
#define N_USERS 4096
#define N_ITEMS 16384
#define L_U     50
#define L_I     20
#define OUT_W   (D_DIM + 2)   // 66
#define N_ROWS  (N_USERS + N_ITEMS)

// One warp computes one output row. Lane l owns columns 2l, 2l+1.
// Canonical best structure (15.136us, reproduced twice). w-gather moved after
// the embedding loop so the idx->w dependency doesn't delay the first gathers.
template <int L, bool IS_USER>
__device__ __forceinline__
void do_row(const float* __restrict__ emb,
            const float* __restrict__ w,
            float                     bias,
            const float* __restrict__ h1,
            const int*   __restrict__ my_idx,
            float*       __restrict__ orow,
            int lane)
{
    int idx_lo = (L >= 32 || lane < L) ? my_idx[lane] : 0;
    int idx_hi = 0;
    if (L > 32) idx_hi = (lane + 32 < L) ? my_idx[lane + 32] : 0;

    float2 h = *reinterpret_cast<const float2*>(h1 + 2 * lane);

    float sx = 0.f, sy = 0.f, qx = 0.f, qy = 0.f;

    #pragma unroll
    for (int j = 0; j < L; ++j) {
        int src = (L <= 32 || j < 32) ? idx_lo : idx_hi;
        int r   = __shfl_sync(0xffffffffu, src, j & 31);
        float2 g = *reinterpret_cast<const float2*>(emb + (size_t)r * D_DIM + 2 * lane);
        sx += g.x; sy += g.y;
        qx += g.x * g.x; qy += g.y * g.y;
    }

    // w-gather after the main loop: latency hides under the shuffle reduce.
    float wsum = 0.f;
    if (L >= 32 || lane < L) wsum += __ldg(&w[idx_lo]);
    if (L > 32 && lane + 32 < L) wsum += __ldg(&w[idx_hi]);

    float part = 0.5f * (sx * sx - qx) * h.x
               + 0.5f * (sy * sy - qy) * h.y + wsum;

    #pragma unroll
    for (int o = 16; o > 0; o >>= 1)
        part += __shfl_xor_sync(0xffffffffu, part, o);

    float2 sv; sv.x = sx; sv.y = sy;
    *reinterpret_cast<float2*>(orow + 2 * lane) = sv;  // stride 66 even -> 8B aligned

    if (lane == 0) {
        if (IS_USER) {
            orow[D_DIM]     = part + bias;
            orow[D_DIM + 1] = 1.0f;
        } else {
            orow[D_DIM]     = 1.0f;
            orow[D_DIM + 1] = part;
        }
    }
}

__global__ __launch_bounds__(256)
void fm_fused_kernel(const float* __restrict__ uemb,
                     const float* __restrict__ iemb,
                     const float* __restrict__ uw,
                     const float* __restrict__ iw,
                     const float* __restrict__ gbias,
                     const float* __restrict__ h1,
                     const float* __restrict__ h2,
                     const int*   __restrict__ uidx,
                     const int*   __restrict__ iidx,
                     float*       __restrict__ out)
{
    const int lane = threadIdx.x & 31;
    const int gw   = (blockIdx.x * blockDim.x + threadIdx.x) >> 5;

    if (blockIdx.x == 0 && threadIdx.x < D_DIM) {
        out[(size_t)N_ROWS * OUT_W + threadIdx.x] = h2[threadIdx.x];
    }

    if (gw < N_USERS) {
        do_row<L_U, true>(uemb, uw, gbias[0], h1,
                          uidx + (size_t)gw * L_U,
                          out + (size_t)gw * OUT_W, lane);
    } else if (gw < N_ROWS) {
        const int row = gw - N_USERS;
        do_row<L_I, false>(iemb, iw, 0.f, h1,
                           iidx + (size_t)row * L_I,
                           out + (size_t)(N_USERS + row) * OUT_W, lane);
    }
}

extern "C" void kernel_launch(void* const* d_in, const int* in_sizes, int n_in,
                              void* d_out, int out_size)
{
    const float* uemb  = (const float*)d_in[0];
    const float* iemb  = (const float*)d_in[1];
    const float* uw    = (const float*)d_in[2];
    const float* iw    = (const float*)d_in[3];
    const float* gbias = (const float*)d_in[4];
    const float* h1    = (const float*)d_in[5];
    const float* h2    = (const float*)d_in[6];
    const int*   uidx  = (const int*)d_in[7];
    const int*   iidx  = (const int*)d_in[8];

    float* out = (float*)d_out;

    const int threads = 256;                 // 8 warps/block (canonical best)
    const int warps_per_block = threads / 32;
    const int blocks = (N_ROWS + warps_per_block - 1) / warps_per_block;  // 2560

    fm_fused_kernel<<<blocks, threads>>>(uemb, iemb, uw, iw, gbias, h1, h2,
                                         uidx, iidx, out);
}

// round 16
// speedup vs baseline: 1.1176x; 1.0651x over previous
#include <cuda_runtime.h>
#include <cstddef>

#define D_DIM   64
#define N_USERS 4096
#define N_ITEMS 16384
#define L_U     50
#define L_I     20
#define OUT_W   (D_DIM + 2)   // 66
#define N_ROWS  (N_USERS + N_ITEMS)
#define THREADS 128           // 4 warps/block (canonical best, 15.136us)

// One warp computes one output row. Lane l owns columns 2l, 2l+1.
// Canonical best body: proven at 15.136us (twice: 256- and 128-thread blocks).
template <int L, bool IS_USER>
__device__ __forceinline__
void do_row(const float* __restrict__ emb,
            const float* __restrict__ w,
            float                     bias,
            const float* __restrict__ h1,
            const int*   __restrict__ my_idx,
            float*       __restrict__ orow,
            int lane)
{
    int idx_lo = (L >= 32 || lane < L) ? my_idx[lane] : 0;
    int idx_hi = 0;
    if (L > 32) idx_hi = (lane + 32 < L) ? my_idx[lane + 32] : 0;

    float wsum = 0.f;
    if (L >= 32 || lane < L) wsum += __ldg(&w[idx_lo]);
    if (L > 32 && lane + 32 < L) wsum += __ldg(&w[idx_hi]);

    float sx = 0.f, sy = 0.f, qx = 0.f, qy = 0.f;

    #pragma unroll
    for (int j = 0; j < L; ++j) {
        int src = (L <= 32 || j < 32) ? idx_lo : idx_hi;
        int r   = __shfl_sync(0xffffffffu, src, j & 31);
        float2 g = *reinterpret_cast<const float2*>(emb + (size_t)r * D_DIM + 2 * lane);
        sx += g.x; sy += g.y;
        qx += g.x * g.x; qy += g.y * g.y;
    }

    float2 h = *reinterpret_cast<const float2*>(h1 + 2 * lane);
    float part = 0.5f * (sx * sx - qx) * h.x
               + 0.5f * (sy * sy - qy) * h.y + wsum;

    #pragma unroll
    for (int o = 16; o > 0; o >>= 1)
        part += __shfl_xor_sync(0xffffffffu, part, o);

    float2 sv; sv.x = sx; sv.y = sy;
    *reinterpret_cast<float2*>(orow + 2 * lane) = sv;  // stride 66 even -> 8B aligned

    if (lane == 0) {
        if (IS_USER) {
            orow[D_DIM]     = part + bias;
            orow[D_DIM + 1] = 1.0f;
        } else {
            orow[D_DIM]     = 1.0f;
            orow[D_DIM + 1] = part;
        }
    }
}

__global__ __launch_bounds__(THREADS)
void fm_fused_kernel(const float* __restrict__ uemb,
                     const float* __restrict__ iemb,
                     const float* __restrict__ uw,
                     const float* __restrict__ iw,
                     const float* __restrict__ gbias,
                     const float* __restrict__ h1,
                     const float* __restrict__ h2,
                     const int*   __restrict__ uidx,
                     const int*   __restrict__ iidx,
                     float*       __restrict__ out)
{
    const int lane = threadIdx.x & 31;
    const int gw   = (blockIdx.x * blockDim.x + threadIdx.x) >> 5;

    if (blockIdx.x == 0 && threadIdx.x < D_DIM) {
        out[(size_t)N_ROWS * OUT_W + threadIdx.x] = h2[threadIdx.x];
    }

    if (gw < N_USERS) {
        do_row<L_U, true>(uemb, uw, gbias[0], h1,
                          uidx + (size_t)gw * L_U,
                          out + (size_t)gw * OUT_W, lane);
    } else if (gw < N_ROWS) {
        const int row = gw - N_USERS;
        do_row<L_I, false>(iemb, iw, 0.f, h1,
                           iidx + (size_t)row * L_I,
                           out + (size_t)(N_USERS + row) * OUT_W, lane);
    }
}

extern "C" void kernel_launch(void* const* d_in, const int* in_sizes, int n_in,
                              void* d_out, int out_size)
{
    const float* uemb  = (const float*)d_in[0];
    const float* iemb  = (const float*)d_in[1];
    const float* uw    = (const float*)d_in[2];
    const float* iw    = (const float*)d_in[3];
    const float* gbias = (const float*)d_in[4];
    const float* h1    = (const float*)d_in[5];
    const float* h2    = (const float*)d_in[6];
    const int*   uidx  = (const int*)d_in[7];
    const int*   iidx  = (const int*)d_in[8];

    float* out = (float*)d_out;

    const int warps_per_block = THREADS / 32;                              // 4
    const int blocks = (N_ROWS + warps_per_block - 1) / warps_per_block;   // 5120

    fm_fused_kernel<<<blocks, THREADS>>>(uemb, iemb, uw, iw, gbias, h1, h2,
                                         uidx, iidx, out);
}